// round 5
// baseline (speedup 1.0000x reference)
#include <cuda_runtime.h>
#include <cuda_bf16.h>
#include <math.h>
#include <float.h>
#include <stdint.h>

#define NPART 62
#define MM    512
#define DD    256
#define MARGIN 0.2f
#define NTILE 36           // pairs (a<=b) of 8 groups of 64

// smem: 2 buffers x 4 planes x (64 rows x 80B) + sq + reduction scratch
#define PLANE   5120       // 64 * 80
#define BUFSZ   20480      // 4 planes
#define SM_SQ   40960      // 128 floats
#define SM_ROWMIN 41472    // 256 f
#define SM_ROWMAX 42496    // 256 f
#define SM_COLMIN 43520    // 128 f
#define SM_RSUM   44032    // 256 f
#define SM_TOTAL  45056

// global scratch (no allocation allowed)
// g_min[(n*64 + g*8 + slot)*64 + j] : contribution of tile(a,b) to group a
// goes to slot b; to group b goes to slot a -> each group owns slots 0..7.
__device__ float g_min[NPART * 64 * 64];
__device__ float g_hp[NPART * MM];           // written only by diagonal CTAs
__device__ float g_dsum[NPART * NTILE];      // per-tile dist sums (fixed order)

__device__ __forceinline__ uint32_t smem_u32(const void* p) {
    uint32_t a;
    asm("{ .reg .u64 t; cvta.to.shared.u64 t, %1; cvt.u32.u64 %0, t; }" : "=r"(a) : "l"(p));
    return a;
}
__device__ __forceinline__ void ldm_x4(uint32_t* r, uint32_t addr) {
    asm volatile("ldmatrix.sync.aligned.m8n8.x4.shared.b16 {%0,%1,%2,%3}, [%4];"
                 : "=r"(r[0]), "=r"(r[1]), "=r"(r[2]), "=r"(r[3]) : "r"(addr));
}
__device__ __forceinline__ void mma16816(float* c, const uint32_t* a, const uint32_t* b) {
    asm volatile("mma.sync.aligned.m16n8k16.row.col.f32.bf16.bf16.f32 "
                 "{%0,%1,%2,%3}, {%4,%5,%6,%7}, {%8,%9}, {%0,%1,%2,%3};"
                 : "+f"(c[0]), "+f"(c[1]), "+f"(c[2]), "+f"(c[3])
                 : "r"(a[0]), "r"(a[1]), "r"(a[2]), "r"(a[3]), "r"(b[0]), "r"(b[1]));
}
__device__ __forceinline__ void tile_pair(int t, int& a, int& b) {
    int aa = 0, tt = t;
    while (tt >= 8 - aa) { tt -= 8 - aa; aa++; }
    a = aa; b = aa + tt;
}

// convert 4 fp32 -> 2x bf16x2 (hi) + 2x bf16x2 (lo), accumulate exact sq
__device__ __forceinline__ void split4(float4 v, uint32_t& h0, uint32_t& h1,
                                       uint32_t& l0, uint32_t& l1, float& sq) {
    __nv_bfloat162 ha = __floats2bfloat162_rn(v.x, v.y);
    __nv_bfloat162 hb = __floats2bfloat162_rn(v.z, v.w);
    float2 fa = __bfloat1622float2(ha);
    float2 fb = __bfloat1622float2(hb);
    __nv_bfloat162 la = __floats2bfloat162_rn(v.x - fa.x, v.y - fa.y);
    __nv_bfloat162 lb = __floats2bfloat162_rn(v.z - fb.x, v.w - fb.y);
    h0 = *(uint32_t*)&ha; h1 = *(uint32_t*)&hb;
    l0 = *(uint32_t*)&la; l1 = *(uint32_t*)&lb;
    sq += v.x * v.x + v.y * v.y + v.z * v.z + v.w * v.w;
}

// ---------------------------------------------------------------------------
// Fused kernel: CTA = (tile pair t -> (a,b), part n). LDGs fp32 rows, splits
// to hi/lo bf16 planes in smem (software-pipelined with the MMA stage),
// computes the 64x64 gram block, fused dist/min/max epilogue.
// ---------------------------------------------------------------------------
__global__ void __launch_bounds__(256) gemm_kernel(const float* __restrict__ f) {
    extern __shared__ char smem[];
    uint32_t sb = smem_u32(smem);
    const int tid  = threadIdx.x;
    const int wid  = tid >> 5;
    const int lane = tid & 31;
    const int wr = wid >> 2;           // 0..1 : 32-row group
    const int wc = wid & 3;            // 0..3 : 16-col group
    const int t = blockIdx.x;
    const int n = blockIdx.y;
    int a, b; tile_pair(t, a, b);
    const bool diag = (a == b);

    // convert-thread mapping: row = tid>>1 (0..127; 0-63 group a, 64-127 b),
    // half = tid&1 selects k sub-range [half*16, half*16+16) of each chunk.
    const int crow = tid >> 1;
    const int chalf = tid & 1;
    const int cgrp64 = ((crow < 64) ? a : b) * 64 + (crow & 63);
    const float* csrc = f + ((size_t)n * MM + cgrp64) * DD + chalf * 16;
    char* cdst_hi = smem + ((crow < 64) ? 0 : 2 * PLANE) + (crow & 63) * 80 + chalf * 32;
    float sqacc = 0.f;

    float4 v0, v1, v2, v3;
    // prologue: load + convert chunk 0 into buffer 0
    v0 = *(const float4*)(csrc);      v1 = *(const float4*)(csrc + 4);
    v2 = *(const float4*)(csrc + 8);  v3 = *(const float4*)(csrc + 12);
    {
        uint32_t h[4], l[4];
        split4(v0, h[0], h[1], l[0], l[1], sqacc);
        split4(v1, h[2], h[3], l[2], l[3], sqacc);
        *(uint4*)(cdst_hi)          = make_uint4(h[0], h[1], h[2], h[3]);
        *(uint4*)(cdst_hi + PLANE)  = make_uint4(l[0], l[1], l[2], l[3]);
        split4(v2, h[0], h[1], l[0], l[1], sqacc);
        split4(v3, h[2], h[3], l[2], l[3], sqacc);
        *(uint4*)(cdst_hi + 16)         = make_uint4(h[0], h[1], h[2], h[3]);
        *(uint4*)(cdst_hi + PLANE + 16) = make_uint4(l[0], l[1], l[2], l[3]);
    }
    __syncthreads();

    const uint32_t a_off = (uint32_t)(lane & 15) * 80 + (uint32_t)(lane >> 4) * 16;
    const uint32_t b_off = (uint32_t)(wc * 16 + (lane & 7) + ((lane >> 4) & 1) * 8) * 80
                         + (uint32_t)((lane >> 3) & 1) * 16;

    float acc[2][2][4];
#pragma unroll
    for (int mi = 0; mi < 2; mi++)
#pragma unroll
        for (int ni = 0; ni < 2; ni++)
#pragma unroll
            for (int r = 0; r < 4; r++) acc[mi][ni][r] = 0.f;

#pragma unroll 1
    for (int s = 0; s < 8; s++) {
        // prefetch fp32 for next chunk (gives the LDGs the whole MMA stage)
        if (s < 7) {
            const float* src = csrc + (s + 1) * 32;
            v0 = *(const float4*)(src);      v1 = *(const float4*)(src + 4);
            v2 = *(const float4*)(src + 8);  v3 = *(const float4*)(src + 12);
        }

        const uint32_t bufb = sb + (uint32_t)(s & 1) * BUFSZ;
#pragma unroll
        for (int ks = 0; ks < 2; ks++) {
            uint32_t ahi[2][4], alo[2][4], bhi[4], blo[4];
#pragma unroll
            for (int mi = 0; mi < 2; mi++) {
                uint32_t ra = bufb + (uint32_t)(wr * 32 + mi * 16) * 80 + a_off + ks * 32;
                ldm_x4(ahi[mi], ra);
                ldm_x4(alo[mi], ra + PLANE);
            }
            {
                uint32_t rb = bufb + 2 * PLANE + b_off + ks * 32;
                ldm_x4(bhi, rb);
                ldm_x4(blo, rb + PLANE);
            }
#pragma unroll
            for (int mi = 0; mi < 2; mi++)
#pragma unroll
                for (int ni = 0; ni < 2; ni++) {
                    const int o = ni * 2;
                    mma16816(acc[mi][ni], ahi[mi], &bhi[o]);
                    mma16816(acc[mi][ni], ahi[mi], &blo[o]);
                    mma16816(acc[mi][ni], alo[mi], &bhi[o]);
                }
        }

        if (s < 7) {
            // convert + store into the other buffer (read last at chunk s-1,
            // all readers done at the syncthreads ending iteration s-1)
            char* dst = cdst_hi + (((s + 1) & 1) ? BUFSZ : 0);
            uint32_t h[4], l[4];
            split4(v0, h[0], h[1], l[0], l[1], sqacc);
            split4(v1, h[2], h[3], l[2], l[3], sqacc);
            *(uint4*)(dst)          = make_uint4(h[0], h[1], h[2], h[3]);
            *(uint4*)(dst + PLANE)  = make_uint4(l[0], l[1], l[2], l[3]);
            split4(v2, h[0], h[1], l[0], l[1], sqacc);
            split4(v3, h[2], h[3], l[2], l[3], sqacc);
            *(uint4*)(dst + 16)         = make_uint4(h[0], h[1], h[2], h[3]);
            *(uint4*)(dst + PLANE + 16) = make_uint4(l[0], l[1], l[2], l[3]);
        }
        __syncthreads();
    }

    // finalize exact fp32 row norms: combine the two k-halves
    {
        float s2 = sqacc + __shfl_xor_sync(0xFFFFFFFFu, sqacc, 1);
        if (chalf == 0) ((float*)(smem + SM_SQ))[crow] = s2;
    }
    __syncthreads();

    // ---- epilogue ----
    const float* sq_s = (const float*)(smem + SM_SQ);
    float rmin[4], rmax[4], cmin[4];
#pragma unroll
    for (int i = 0; i < 4; i++) { rmin[i] = FLT_MAX; rmax[i] = -FLT_MAX; cmin[i] = FLT_MAX; }
    float dsum = 0.f;

#pragma unroll
    for (int mi = 0; mi < 2; mi++)
#pragma unroll
        for (int ni = 0; ni < 2; ni++)
#pragma unroll
            for (int r = 0; r < 4; r++) {
                const int rowl = wr * 32 + mi * 16 + (r >> 1) * 8 + (lane >> 2);
                const int col  = wc * 16 + ni * 8 + (lane & 3) * 2 + (r & 1);
                float d2 = sq_s[rowl] + sq_s[64 + col] - 2.f * acc[mi][ni][r];
                float dist = sqrtf(fmaxf(d2, 0.f));
                dsum += dist;
                const int rs = mi * 2 + (r >> 1);
                const int cs = ni * 2 + (r & 1);
                if (diag) {
                    if ((rowl >> 3) == (col >> 3)) rmax[rs] = fmaxf(rmax[rs], dist);
                    else                           rmin[rs] = fminf(rmin[rs], dist);
                } else {
                    rmin[rs] = fminf(rmin[rs], dist);
                    cmin[cs] = fminf(cmin[cs], dist);
                }
            }

    float* rowmin = (float*)(smem + SM_ROWMIN);
    float* rowmax = (float*)(smem + SM_ROWMAX);
    float* colmin = (float*)(smem + SM_COLMIN);
    float* rsum   = (float*)(smem + SM_RSUM);

#pragma unroll
    for (int s2 = 0; s2 < 4; s2++) {
        float rm = rmin[s2], rx = rmax[s2];
        rm = fminf(rm, __shfl_xor_sync(0xFFFFFFFFu, rm, 1));
        rm = fminf(rm, __shfl_xor_sync(0xFFFFFFFFu, rm, 2));
        rx = fmaxf(rx, __shfl_xor_sync(0xFFFFFFFFu, rx, 1));
        rx = fmaxf(rx, __shfl_xor_sync(0xFFFFFFFFu, rx, 2));
        if ((lane & 3) == 0) {
            const int row = wr * 32 + (s2 >> 1) * 16 + (s2 & 1) * 8 + (lane >> 2);
            rowmin[row * 4 + wc] = rm;
            rowmax[row * 4 + wc] = rx;
        }
        float cm = cmin[s2];
        cm = fminf(cm, __shfl_xor_sync(0xFFFFFFFFu, cm, 4));
        cm = fminf(cm, __shfl_xor_sync(0xFFFFFFFFu, cm, 8));
        cm = fminf(cm, __shfl_xor_sync(0xFFFFFFFFu, cm, 16));
        if (lane < 4) {
            const int col = wc * 16 + (s2 >> 1) * 8 + (lane & 3) * 2 + (s2 & 1);
            colmin[col * 2 + wr] = cm;
        }
    }
    rsum[tid] = dsum;
    __syncthreads();

    if (tid < 64) {
        float rn = FLT_MAX, rp = -FLT_MAX;
#pragma unroll
        for (int c = 0; c < 4; c++) {
            rn = fminf(rn, rowmin[tid * 4 + c]);
            rp = fmaxf(rp, rowmax[tid * 4 + c]);
        }
        g_min[(n * 64 + a * 8 + b) * 64 + tid] = rn;       // slot b of group a
        if (diag) g_hp[n * MM + a * 64 + tid] = rp;
    } else if (tid < 128 && !diag) {
        const int j = tid - 64;
        float cm = fminf(colmin[j * 2], colmin[j * 2 + 1]);
        g_min[(n * 64 + b * 8 + a) * 64 + j] = cm;         // slot a of group b
    }
    __syncthreads();
    for (int s = 128; s > 0; s >>= 1) {
        if (tid < s) rsum[tid] += rsum[tid + s];
        __syncthreads();
    }
    if (tid == 0) g_dsum[n * NTILE + t] = rsum[0];
}

// ---------------------------------------------------------------------------
// Finish: per part, loss mean (min over the 8 owned slots per row) + dist
// mean from tile sums (off-diagonal twice). Fixed reduction trees.
// ---------------------------------------------------------------------------
__global__ void finish_kernel(float* __restrict__ out) {
    __shared__ float wsum[8];
    const int n = blockIdx.x;
    const int tid = threadIdx.x;
    const int lane = tid & 31;
    float l = 0.f;
#pragma unroll
    for (int h = 0; h < 2; h++) {
        const int row = tid + h * 256;
        const int g = row >> 6, j = row & 63;
        float mn = FLT_MAX;
#pragma unroll
        for (int s = 0; s < 8; s++)
            mn = fminf(mn, g_min[(n * 64 + g * 8 + s) * 64 + j]);
        l += fmaxf(MARGIN + g_hp[n * MM + row] - mn, 0.f);
    }
#pragma unroll
    for (int o = 16; o; o >>= 1) l += __shfl_xor_sync(0xFFFFFFFFu, l, o);
    if (lane == 0) wsum[tid >> 5] = l;
    __syncthreads();
    if (tid < 32) {
        float d = 0.f;
        if (lane < NTILE) {
            int aa, bb; tile_pair(lane, aa, bb);
            d = g_dsum[n * NTILE + lane] * ((aa == bb) ? 1.f : 2.f);
        }
        if (lane < NTILE - 32) {
            int aa, bb; tile_pair(lane + 32, aa, bb);
            d += g_dsum[n * NTILE + lane + 32] * ((aa == bb) ? 1.f : 2.f);
        }
#pragma unroll
        for (int o = 16; o; o >>= 1) d += __shfl_xor_sync(0xFFFFFFFFu, d, o);
        if (lane == 0) {
            float ls = 0.f;
#pragma unroll
            for (int w = 0; w < 8; w++) ls += wsum[w];
            out[n]         = ls / (float)MM;
            out[NPART + n] = d / ((float)MM * (float)MM);
        }
    }
}

extern "C" void kernel_launch(void* const* d_in, const int* in_sizes, int n_in,
                              void* d_out, int out_size) {
    const float* feature = (const float*)d_in[0];
    float* out = (float*)d_out;

    cudaFuncSetAttribute(gemm_kernel, cudaFuncAttributeMaxDynamicSharedMemorySize, SM_TOTAL);

    dim3 grid(NTILE, NPART);
    gemm_kernel<<<grid, 256, SM_TOTAL>>>(feature);

    finish_kernel<<<NPART, 256>>>(out);
}

// round 6
// speedup vs baseline: 1.4625x; 1.4625x over previous
#include <cuda_runtime.h>
#include <cuda_bf16.h>
#include <math.h>
#include <float.h>
#include <stdint.h>

#define NPART 62
#define MM    512
#define DD    256
#define MARGIN 0.2f
#define NTILE 36           // pairs (a<=b) of 8 groups of 64

// smem: 2 buffers x 4 planes x (64 rows x 80B) + sq + reduction scratch
#define PLANE   5120       // 64 * 80
#define BUFSZ   20480      // 4 planes
#define SM_SQ   40960      // 128 floats
#define SM_ROWMIN 41472    // 64*2 f
#define SM_ROWMAX 41984    // 64*2 f
#define SM_COLMIN 42496    // 64*2 f
#define SM_RSUM   43008    // 128 f
#define SM_TOTAL  43520

// global scratch (no allocation allowed)
// g_min[(n*64 + g*8 + slot)*64 + j]: tile(a,b) writes group-a row-mins to
// slot b and group-b col-mins to slot a -> every group owns slots 0..7,
// single writer per slot, deterministic, no init needed.
__device__ float g_min[NPART * 64 * 64];
__device__ float g_hp[NPART * MM];           // written only by diagonal CTAs
__device__ float g_dsum[NPART * NTILE];      // per-tile dist sums (fixed order)
__device__ __align__(16) __nv_bfloat16 g_hi[(size_t)NPART * MM * DD];
__device__ __align__(16) __nv_bfloat16 g_lo[(size_t)NPART * MM * DD];
__device__ __align__(16) float g_sq[NPART * MM];

__device__ __forceinline__ uint32_t smem_u32(const void* p) {
    uint32_t a;
    asm("{ .reg .u64 t; cvta.to.shared.u64 t, %1; cvt.u32.u64 %0, t; }" : "=r"(a) : "l"(p));
    return a;
}
__device__ __forceinline__ void cp16(uint32_t dst, const void* src) {
    asm volatile("cp.async.cg.shared.global [%0], [%1], 16;" :: "r"(dst), "l"(src));
}
#define CP_COMMIT() asm volatile("cp.async.commit_group;" ::: "memory")
#define CP_WAIT(n)  asm volatile("cp.async.wait_group %0;" :: "n"(n) : "memory")

__device__ __forceinline__ void ldm_x4(uint32_t* r, uint32_t addr) {
    asm volatile("ldmatrix.sync.aligned.m8n8.x4.shared.b16 {%0,%1,%2,%3}, [%4];"
                 : "=r"(r[0]), "=r"(r[1]), "=r"(r[2]), "=r"(r[3]) : "r"(addr));
}
__device__ __forceinline__ void mma16816(float* c, const uint32_t* a, const uint32_t* b) {
    asm volatile("mma.sync.aligned.m16n8k16.row.col.f32.bf16.bf16.f32 "
                 "{%0,%1,%2,%3}, {%4,%5,%6,%7}, {%8,%9}, {%0,%1,%2,%3};"
                 : "+f"(c[0]), "+f"(c[1]), "+f"(c[2]), "+f"(c[3])
                 : "r"(a[0]), "r"(a[1]), "r"(a[2]), "r"(a[3]), "r"(b[0]), "r"(b[1]));
}
__device__ __forceinline__ void tile_pair(int t, int& a, int& b) {
    int aa = 0, tt = t;
    while (tt >= 8 - aa) { tt -= 8 - aa; aa++; }
    a = aa; b = aa + tt;
}

// ---------------------------------------------------------------------------
// Kernel 1: per row: exact fp32 sq-norm + split-bf16 hi/lo planes.
// ---------------------------------------------------------------------------
__global__ void prep_kernel(const float* __restrict__ f) {
    int row = blockIdx.x * blockDim.y + threadIdx.y;
    if (row >= NPART * MM) return;
    int lane = threadIdx.x;
    const float4* p = (const float4*)(f + (size_t)row * DD);
    float s = 0.f;
#pragma unroll
    for (int q = 0; q < 2; q++) {
        float4 v = p[lane + q * 32];
        int col = (lane + q * 32) * 4;
        __nv_bfloat162 h01 = __floats2bfloat162_rn(v.x, v.y);
        __nv_bfloat162 h23 = __floats2bfloat162_rn(v.z, v.w);
        float2 f01 = __bfloat1622float2(h01);
        float2 f23 = __bfloat1622float2(h23);
        __nv_bfloat162 l01 = __floats2bfloat162_rn(v.x - f01.x, v.y - f01.y);
        __nv_bfloat162 l23 = __floats2bfloat162_rn(v.z - f23.x, v.w - f23.y);
        size_t off = (size_t)row * DD + col;
        *(__nv_bfloat162*)(g_hi + off)     = h01;
        *(__nv_bfloat162*)(g_hi + off + 2) = h23;
        *(__nv_bfloat162*)(g_lo + off)     = l01;
        *(__nv_bfloat162*)(g_lo + off + 2) = l23;
        s += v.x * v.x + v.y * v.y + v.z * v.z + v.w * v.w;
    }
#pragma unroll
    for (int o = 16; o; o >>= 1) s += __shfl_xor_sync(0xFFFFFFFFu, s, o);
    if (lane == 0) g_sq[row] = s;
}

// ---------------------------------------------------------------------------
// Kernel 2: CTA = (tile pair t -> (a,b) with a<=b, part n). 128 threads,
// 4 warps in a 2x2 grid of 32x32 warp tiles (fat tiles -> 1.5x less smem
// read per HMMA). K=256 in 8 chunks of 32, double-buffered cp.async.
// ---------------------------------------------------------------------------
__global__ void __launch_bounds__(128) gemm_kernel() {
    extern __shared__ char smem[];
    uint32_t sb = smem_u32(smem);
    const int tid  = threadIdx.x;
    const int wid  = tid >> 5;
    const int lane = tid & 31;
    const int wr = wid >> 1;           // 0..1 : 32-row group
    const int wc = wid & 1;            // 0..1 : 32-col group
    const int t = blockIdx.x;
    const int n = blockIdx.y;
    int a, b; tile_pair(t, a, b);
    const bool diag = (a == b);

    const __nv_bfloat16* hi_n = g_hi + (size_t)n * MM * DD;
    const __nv_bfloat16* lo_n = g_lo + (size_t)n * MM * DD;

    // ---- prologue: sq for both groups + k-chunk 0 ----
    if (tid < 32) {
        int grp = (tid < 16) ? a : b;
        int q = tid & 15;
        cp16(sb + SM_SQ + tid * 16, g_sq + n * MM + grp * 64 + q * 4);
    }
#pragma unroll
    for (int c = tid; c < 1024; c += 128) {
        int plane = c >> 8, idx = c & 255;
        int r = idx >> 2, q = idx & 3;
        int grp = (plane < 2) ? a : b;
        const __nv_bfloat16* src =
            ((plane & 1) ? lo_n : hi_n) + (size_t)(grp * 64 + r) * DD + q * 8;
        cp16(sb + plane * PLANE + r * 80 + q * 16, src);
    }
    CP_COMMIT();

    const uint32_t a_off = (uint32_t)(lane & 15) * 80 + (uint32_t)(lane >> 4) * 16;
    const uint32_t b_off = (uint32_t)((lane & 7) + ((lane >> 4) & 1) * 8) * 80
                         + (uint32_t)((lane >> 3) & 1) * 16;

    float acc[2][4][4];
#pragma unroll
    for (int mi = 0; mi < 2; mi++)
#pragma unroll
        for (int ni = 0; ni < 4; ni++)
#pragma unroll
            for (int r = 0; r < 4; r++) acc[mi][ni][r] = 0.f;

#pragma unroll 1
    for (int s = 0; s < 8; s++) {
        if (s < 7) {
            const int k0 = (s + 1) * 32;
            const uint32_t bufn = (uint32_t)((s + 1) & 1) * BUFSZ;
#pragma unroll
            for (int c = tid; c < 1024; c += 128) {
                int plane = c >> 8, idx = c & 255;
                int r = idx >> 2, q = idx & 3;
                int grp = (plane < 2) ? a : b;
                const __nv_bfloat16* src =
                    ((plane & 1) ? lo_n : hi_n) + (size_t)(grp * 64 + r) * DD + k0 + q * 8;
                cp16(sb + bufn + plane * PLANE + r * 80 + q * 16, src);
            }
            CP_COMMIT();
            CP_WAIT(1);
        } else {
            CP_WAIT(0);
        }
        __syncthreads();

        const uint32_t bufb = sb + (uint32_t)(s & 1) * BUFSZ;
#pragma unroll
        for (int ks = 0; ks < 2; ks++) {
            uint32_t ahi[2][4], alo[2][4], bhi[2][4], blo[2][4];
#pragma unroll
            for (int mi = 0; mi < 2; mi++) {
                uint32_t ra = bufb + (uint32_t)(wr * 32 + mi * 16) * 80 + a_off + ks * 32;
                ldm_x4(ahi[mi], ra);
                ldm_x4(alo[mi], ra + PLANE);
            }
#pragma unroll
            for (int g = 0; g < 2; g++) {
                uint32_t rb = bufb + 2 * PLANE + (uint32_t)(wc * 32 + g * 16) * 80
                            + b_off + ks * 32;
                ldm_x4(bhi[g], rb);
                ldm_x4(blo[g], rb + PLANE);
            }
#pragma unroll
            for (int mi = 0; mi < 2; mi++)
#pragma unroll
                for (int ni = 0; ni < 4; ni++) {
                    const int g = ni >> 1, o = (ni & 1) * 2;
                    mma16816(acc[mi][ni], ahi[mi], &bhi[g][o]);
                    mma16816(acc[mi][ni], ahi[mi], &blo[g][o]);
                    mma16816(acc[mi][ni], alo[mi], &bhi[g][o]);
                }
        }
        __syncthreads();
    }

    // ---- epilogue ----
    const float* sq_s = (const float*)(smem + SM_SQ);
    float rmin[4], rmax[4], cmin[8];
#pragma unroll
    for (int i = 0; i < 4; i++) { rmin[i] = FLT_MAX; rmax[i] = -FLT_MAX; }
#pragma unroll
    for (int i = 0; i < 8; i++) cmin[i] = FLT_MAX;
    float dsum = 0.f;

#pragma unroll
    for (int mi = 0; mi < 2; mi++)
#pragma unroll
        for (int ni = 0; ni < 4; ni++)
#pragma unroll
            for (int r = 0; r < 4; r++) {
                const int rowl = wr * 32 + mi * 16 + (r >> 1) * 8 + (lane >> 2);
                const int col  = wc * 32 + ni * 8 + (lane & 3) * 2 + (r & 1);
                float d2 = sq_s[rowl] + sq_s[64 + col] - 2.f * acc[mi][ni][r];
                float dist = sqrtf(fmaxf(d2, 0.f));
                dsum += dist;
                const int rs = mi * 2 + (r >> 1);
                const int cs = ni * 2 + (r & 1);
                if (diag) {
                    if ((rowl >> 3) == (col >> 3)) rmax[rs] = fmaxf(rmax[rs], dist);
                    else                           rmin[rs] = fminf(rmin[rs], dist);
                } else {
                    rmin[rs] = fminf(rmin[rs], dist);
                    cmin[cs] = fminf(cmin[cs], dist);
                }
            }

    float* rowmin = (float*)(smem + SM_ROWMIN);
    float* rowmax = (float*)(smem + SM_ROWMAX);
    float* colmin = (float*)(smem + SM_COLMIN);
    float* rsum   = (float*)(smem + SM_RSUM);

#pragma unroll
    for (int s2 = 0; s2 < 4; s2++) {
        float rm = rmin[s2], rx = rmax[s2];
        rm = fminf(rm, __shfl_xor_sync(0xFFFFFFFFu, rm, 1));
        rm = fminf(rm, __shfl_xor_sync(0xFFFFFFFFu, rm, 2));
        rx = fmaxf(rx, __shfl_xor_sync(0xFFFFFFFFu, rx, 1));
        rx = fmaxf(rx, __shfl_xor_sync(0xFFFFFFFFu, rx, 2));
        if ((lane & 3) == 0) {
            const int row = wr * 32 + (s2 >> 1) * 16 + (s2 & 1) * 8 + (lane >> 2);
            rowmin[row * 2 + wc] = rm;
            rowmax[row * 2 + wc] = rx;
        }
    }
#pragma unroll
    for (int s2 = 0; s2 < 8; s2++) {
        float cm = cmin[s2];
        cm = fminf(cm, __shfl_xor_sync(0xFFFFFFFFu, cm, 4));
        cm = fminf(cm, __shfl_xor_sync(0xFFFFFFFFu, cm, 8));
        cm = fminf(cm, __shfl_xor_sync(0xFFFFFFFFu, cm, 16));
        if (lane < 4) {
            const int col = wc * 32 + (s2 >> 1) * 8 + (lane & 3) * 2 + (s2 & 1);
            colmin[col * 2 + wr] = cm;
        }
    }
    rsum[tid] = dsum;
    __syncthreads();

    if (tid < 64) {
        float rn = fminf(rowmin[tid * 2], rowmin[tid * 2 + 1]);
        float rp = fmaxf(rowmax[tid * 2], rowmax[tid * 2 + 1]);
        g_min[(n * 64 + a * 8 + b) * 64 + tid] = rn;       // slot b of group a
        if (diag) g_hp[n * MM + a * 64 + tid] = rp;
    } else if (!diag) {
        const int j = tid - 64;
        float cm = fminf(colmin[j * 2], colmin[j * 2 + 1]);
        g_min[(n * 64 + b * 8 + a) * 64 + j] = cm;         // slot a of group b
    }
    __syncthreads();
    for (int s = 64; s > 0; s >>= 1) {
        if (tid < s) rsum[tid] += rsum[tid + s];
        __syncthreads();
    }
    if (tid == 0) g_dsum[n * NTILE + t] = rsum[0];
}

// ---------------------------------------------------------------------------
// Finish: per part, loss mean (min over the 8 owned slots per row) + dist
// mean from tile sums (off-diagonal twice). Fixed reduction trees.
// ---------------------------------------------------------------------------
__global__ void finish_kernel(float* __restrict__ out) {
    __shared__ float wsum[8];
    const int n = blockIdx.x;
    const int tid = threadIdx.x;
    const int lane = tid & 31;
    float l = 0.f;
#pragma unroll
    for (int h = 0; h < 2; h++) {
        const int row = tid + h * 256;
        const int g = row >> 6, j = row & 63;
        float mn = FLT_MAX;
#pragma unroll
        for (int s = 0; s < 8; s++)
            mn = fminf(mn, g_min[(n * 64 + g * 8 + s) * 64 + j]);
        l += fmaxf(MARGIN + g_hp[n * MM + row] - mn, 0.f);
    }
#pragma unroll
    for (int o = 16; o; o >>= 1) l += __shfl_xor_sync(0xFFFFFFFFu, l, o);
    if (lane == 0) wsum[tid >> 5] = l;
    __syncthreads();
    if (tid < 32) {
        float d = 0.f;
        if (lane < NTILE) {
            int aa, bb; tile_pair(lane, aa, bb);
            d = g_dsum[n * NTILE + lane] * ((aa == bb) ? 1.f : 2.f);
        }
        if (lane < NTILE - 32) {
            int aa, bb; tile_pair(lane + 32, aa, bb);
            d += g_dsum[n * NTILE + lane + 32] * ((aa == bb) ? 1.f : 2.f);
        }
#pragma unroll
        for (int o = 16; o; o >>= 1) d += __shfl_xor_sync(0xFFFFFFFFu, d, o);
        if (lane == 0) {
            float ls = 0.f;
#pragma unroll
            for (int w = 0; w < 8; w++) ls += wsum[w];
            out[n]         = ls / (float)MM;
            out[NPART + n] = d / ((float)MM * (float)MM);
        }
    }
}

extern "C" void kernel_launch(void* const* d_in, const int* in_sizes, int n_in,
                              void* d_out, int out_size) {
    const float* feature = (const float*)d_in[0];
    float* out = (float*)d_out;

    cudaFuncSetAttribute(gemm_kernel, cudaFuncAttributeMaxDynamicSharedMemorySize, SM_TOTAL);

    dim3 b1(32, 8);
    prep_kernel<<<(NPART * MM + 7) / 8, b1>>>(feature);

    dim3 grid(NTILE, NPART);
    gemm_kernel<<<grid, 128, SM_TOTAL>>>();

    finish_kernel<<<NPART, 256>>>(out);
}